// round 2
// baseline (speedup 1.0000x reference)
#include <cuda_runtime.h>
#include <cuda_bf16.h>

// SE3Transform (PARTIAL_DENSE): for m in [0,M), i in [0,N):
//   nb = batch[i] + m*B;  out_pos[m*N+i] = R[nb] @ xyz[i] + p[nb];  out_batch[m*N+i] = nb
// Inputs (metadata order): trans [M*B,4,4] f32, xyz [N,3] f32, batch [N] i32.
// Output buffer: new_pos.ravel() [M*N*3] f32, optionally followed by new_batch
// [M*N] (as float) when out_size covers it.

#define BATCH_B 16

__global__ void __launch_bounds__(256) se3_kernel(
        const float4* __restrict__ trans4,
        const float4* __restrict__ xyz4,
        const float*  __restrict__ xyz,
        const int4*   __restrict__ batch4,
        const int*    __restrict__ batch,
        float* __restrict__ out,
        int N, int G,
        long long posElems, int writeBatch)
{
    const int m = blockIdx.y;                 // replica index [0, M)
    const int mB = m * BATCH_B;
    const long long sliceBase = (long long)m * N;

    for (int g = blockIdx.x * blockDim.x + threadIdx.x; g < G;
         g += gridDim.x * blockDim.x)
    {
        const int i0 = g * 4;

        if (i0 + 3 < N) {
            // ---- fast path: 4 points, all 16B-vector LD/ST ----
            float4 a = __ldg(&xyz4[g * 3 + 0]);
            float4 b = __ldg(&xyz4[g * 3 + 1]);
            float4 c = __ldg(&xyz4[g * 3 + 2]);
            int4  bt = __ldg(&batch4[g]);

            float x[4], y[4], z[4];
            x[0] = a.x; y[0] = a.y; z[0] = a.z;
            x[1] = a.w; y[1] = b.x; z[1] = b.y;
            x[2] = b.z; y[2] = b.w; z[2] = c.x;
            x[3] = c.y; y[3] = c.z; z[3] = c.w;

            int nb[4];
            nb[0] = bt.x + mB;
            nb[1] = bt.y + mB;
            nb[2] = bt.z + mB;
            nb[3] = bt.w + mB;

            float o[12];
            #pragma unroll
            for (int k = 0; k < 4; k++) {
                float4 r0 = __ldg(&trans4[nb[k] * 4 + 0]);
                float4 r1 = __ldg(&trans4[nb[k] * 4 + 1]);
                float4 r2 = __ldg(&trans4[nb[k] * 4 + 2]);
                o[k*3+0] = fmaf(r0.x, x[k], fmaf(r0.y, y[k], fmaf(r0.z, z[k], r0.w)));
                o[k*3+1] = fmaf(r1.x, x[k], fmaf(r1.y, y[k], fmaf(r1.z, z[k], r1.w)));
                o[k*3+2] = fmaf(r2.x, x[k], fmaf(r2.y, y[k], fmaf(r2.z, z[k], r2.w)));
            }

            // (m*N + i0)*3 is a multiple of 4 when i0 % 4 == 0 and N % 4 == 0
            float4* outv = (float4*)(out + (sliceBase + i0) * 3);
            outv[0] = make_float4(o[0], o[1], o[2],  o[3]);
            outv[1] = make_float4(o[4], o[5], o[6],  o[7]);
            outv[2] = make_float4(o[8], o[9], o[10], o[11]);

            if (writeBatch) {
                float4* bo = (float4*)(out + posElems + sliceBase + i0);
                *bo = make_float4((float)nb[0], (float)nb[1],
                                  (float)nb[2], (float)nb[3]);
            }
        } else {
            // ---- scalar tail (N % 4 != 0 or last partial group) ----
            for (int i = i0; i < N; i++) {
                float px = xyz[i * 3 + 0];
                float py = xyz[i * 3 + 1];
                float pz = xyz[i * 3 + 2];
                int nbi = __ldg(&batch[i]) + mB;
                float4 r0 = __ldg(&trans4[nbi * 4 + 0]);
                float4 r1 = __ldg(&trans4[nbi * 4 + 1]);
                float4 r2 = __ldg(&trans4[nbi * 4 + 2]);
                long long ob = (sliceBase + i) * 3;
                out[ob + 0] = fmaf(r0.x, px, fmaf(r0.y, py, fmaf(r0.z, pz, r0.w)));
                out[ob + 1] = fmaf(r1.x, px, fmaf(r1.y, py, fmaf(r1.z, pz, r1.w)));
                out[ob + 2] = fmaf(r2.x, px, fmaf(r2.y, py, fmaf(r2.z, pz, r2.w)));
                if (writeBatch)
                    out[posElems + sliceBase + i] = (float)nbi;
            }
        }
    }
}

extern "C" void kernel_launch(void* const* d_in, const int* in_sizes, int n_in,
                              void* d_out, int out_size) {
    const float* trans = (const float*)d_in[0];   // [M*B, 4, 4]
    const float* xyz   = (const float*)d_in[1];   // [N, 3]
    const int*   batch = (const int*)d_in[2];     // [N]

    int numMat = in_sizes[0] / 16;        // M*B (= 128)
    int M      = numMat / BATCH_B;        // 8
    int N      = in_sizes[2];             // 500000

    long long posElems = (long long)M * N * 3;
    int writeBatch = ((long long)out_size >= posElems + (long long)M * N) ? 1 : 0;

    int G = (N + 3) / 4;                  // 4-point groups per replica
    int threads = 256;
    int blocksX = (G + threads - 1) / threads;
    if (blocksX > 65535) blocksX = 65535; // grid-stride covers the rest

    dim3 grid(blocksX, M, 1);
    se3_kernel<<<grid, threads>>>(
        (const float4*)trans,
        (const float4*)xyz, xyz,
        (const int4*)batch, batch,
        (float*)d_out,
        N, G, posElems, writeBatch);
}

// round 3
// speedup vs baseline: 1.2369x; 1.2369x over previous
#include <cuda_runtime.h>
#include <cuda_bf16.h>

// SE3Transform (PARTIAL_DENSE): for m in [0,M), i in [0,N):
//   nb = batch[i] + m*B;  out_pos[m*N+i] = R[nb] @ xyz[i] + p[nb];  out_batch[m*N+i] = nb
// Inputs: trans [M*B,4,4] f32, xyz [N,3] f32, batch [N] i32.
// Output: new_pos.ravel() [M*N*3] f32 ++ new_batch [M*N] as f32.
//
// R2 finding: L1tex 77% bound by divergent LDG.128 gathers into the 8KB trans
// table. R3: gather from shared memory instead, padded to 80B/matrix so base
// banks spread (stride 64B would alias all rows to banks 0/16).

#define BATCH_B 16
#define NMAT    128          // M*B
#define SLOT    5            // float4 per matrix in smem (3 rows + 2 pad)

__global__ void __launch_bounds__(256) se3_kernel(
        const float4* __restrict__ trans4,
        const float4* __restrict__ xyz4,
        const float*  __restrict__ xyz,
        const int4*   __restrict__ batch4,
        const int*    __restrict__ batch,
        float* __restrict__ out,
        int N, int G,
        long long posElems, int writeBatch)
{
    __shared__ float4 s_trans[NMAT * SLOT];   // 10240 B

    // Cooperative load of the 128 matrices' top-3 rows (each row = [Rx,Ry,Rz,p]).
    for (int idx = threadIdx.x; idx < NMAT * 3; idx += blockDim.x) {
        int mat = idx / 3;
        int row = idx - mat * 3;
        s_trans[mat * SLOT + row] = __ldg(&trans4[mat * 4 + row]);
    }
    __syncthreads();

    const int m = blockIdx.y;                 // replica index [0, M)
    const int mB = m * BATCH_B;
    const long long sliceBase = (long long)m * N;

    for (int g = blockIdx.x * blockDim.x + threadIdx.x; g < G;
         g += gridDim.x * blockDim.x)
    {
        const int i0 = g * 4;

        if (i0 + 3 < N) {
            // ---- fast path: 4 points ----
            float4 a = __ldg(&xyz4[g * 3 + 0]);
            float4 b = __ldg(&xyz4[g * 3 + 1]);
            float4 c = __ldg(&xyz4[g * 3 + 2]);
            int4  bt = __ldg(&batch4[g]);

            float x[4], y[4], z[4];
            x[0] = a.x; y[0] = a.y; z[0] = a.z;
            x[1] = a.w; y[1] = b.x; z[1] = b.y;
            x[2] = b.z; y[2] = b.w; z[2] = c.x;
            x[3] = c.y; y[3] = c.z; z[3] = c.w;

            int nb[4];
            nb[0] = bt.x + mB;
            nb[1] = bt.y + mB;
            nb[2] = bt.z + mB;
            nb[3] = bt.w + mB;

            float o[12];
            #pragma unroll
            for (int k = 0; k < 4; k++) {
                const float4* mrow = &s_trans[nb[k] * SLOT];
                float4 r0 = mrow[0];
                float4 r1 = mrow[1];
                float4 r2 = mrow[2];
                o[k*3+0] = fmaf(r0.x, x[k], fmaf(r0.y, y[k], fmaf(r0.z, z[k], r0.w)));
                o[k*3+1] = fmaf(r1.x, x[k], fmaf(r1.y, y[k], fmaf(r1.z, z[k], r1.w)));
                o[k*3+2] = fmaf(r2.x, x[k], fmaf(r2.y, y[k], fmaf(r2.z, z[k], r2.w)));
            }

            float4* outv = (float4*)(out + (sliceBase + i0) * 3);
            outv[0] = make_float4(o[0], o[1], o[2],  o[3]);
            outv[1] = make_float4(o[4], o[5], o[6],  o[7]);
            outv[2] = make_float4(o[8], o[9], o[10], o[11]);

            if (writeBatch) {
                float4* bo = (float4*)(out + posElems + sliceBase + i0);
                *bo = make_float4((float)nb[0], (float)nb[1],
                                  (float)nb[2], (float)nb[3]);
            }
        } else {
            // ---- scalar tail ----
            for (int i = i0; i < N; i++) {
                float px = xyz[i * 3 + 0];
                float py = xyz[i * 3 + 1];
                float pz = xyz[i * 3 + 2];
                int nbi = __ldg(&batch[i]) + mB;
                float4 r0 = s_trans[nbi * SLOT + 0];
                float4 r1 = s_trans[nbi * SLOT + 1];
                float4 r2 = s_trans[nbi * SLOT + 2];
                long long ob = (sliceBase + i) * 3;
                out[ob + 0] = fmaf(r0.x, px, fmaf(r0.y, py, fmaf(r0.z, pz, r0.w)));
                out[ob + 1] = fmaf(r1.x, px, fmaf(r1.y, py, fmaf(r1.z, pz, r1.w)));
                out[ob + 2] = fmaf(r2.x, px, fmaf(r2.y, py, fmaf(r2.z, pz, r2.w)));
                if (writeBatch)
                    out[posElems + sliceBase + i] = (float)nbi;
            }
        }
    }
}

extern "C" void kernel_launch(void* const* d_in, const int* in_sizes, int n_in,
                              void* d_out, int out_size) {
    const float* trans = (const float*)d_in[0];   // [M*B, 4, 4]
    const float* xyz   = (const float*)d_in[1];   // [N, 3]
    const int*   batch = (const int*)d_in[2];     // [N]

    int numMat = in_sizes[0] / 16;        // M*B (= 128)
    int M      = numMat / BATCH_B;        // 8
    int N      = in_sizes[2];             // 500000

    long long posElems = (long long)M * N * 3;
    int writeBatch = ((long long)out_size >= posElems + (long long)M * N) ? 1 : 0;

    int G = (N + 3) / 4;                  // 4-point groups per replica
    int threads = 256;
    int blocksX = (G + threads - 1) / threads;
    if (blocksX > 65535) blocksX = 65535;

    dim3 grid(blocksX, M, 1);
    se3_kernel<<<grid, threads>>>(
        (const float4*)trans,
        (const float4*)xyz, xyz,
        (const int4*)batch, batch,
        (float*)d_out,
        N, G, posElems, writeBatch);
}

// round 4
// speedup vs baseline: 1.4717x; 1.1898x over previous
#include <cuda_runtime.h>
#include <cuda_bf16.h>

// SE3Transform (PARTIAL_DENSE): for m in [0,M), i in [0,N):
//   nb = batch[i] + m*B;  out_pos[m*N+i] = R[nb] @ xyz[i] + p[nb];  out_batch[m*N+i] = nb
// Inputs: trans [M*B,4,4] f32, xyz [N,3] f32, batch [N] i32.
// Output: new_pos.ravel() [M*N*3] f32 ++ new_batch [M*N] as f32.
//
// R3 findings: L1tex-bound. Gathers were 2-way bank-conflicted (SLOT=5 float4
// stride: nb and nb+8 alias). Fix: float2-SoA table s2[j][mat] -> per-j lane
// bank = 2*(nb mod 16): conflict-free. Also amortize xyz/batch LDG over 4
// slices per thread.

#define BATCH_B 16
#define NMAT    128          // M*B
#define NPAIR   6            // float2 pairs per matrix (12 floats)
#define SL      4            // slices handled per thread

__global__ void __launch_bounds__(256) se3_kernel(
        const float*  __restrict__ trans,
        const float4* __restrict__ xyz4,
        const float*  __restrict__ xyz,
        const int4*   __restrict__ batch4,
        const int*    __restrict__ batch,
        float* __restrict__ out,
        int N, int G, int M,
        long long posElems, int writeBatch)
{
    // float2-SoA transform table: s2[j*NMAT + mat] = (trans[mat][2j], trans[mat][2j+1])
    // (first 12 floats of each 4x4 = rows 0..2).
    __shared__ float2 s2[NPAIR * NMAT];   // 6 KB

    for (int idx = threadIdx.x; idx < NPAIR * NMAT; idx += blockDim.x) {
        int j   = idx >> 7;          // idx / 128
        int mat = idx & 127;         // idx % 128
        const float2* src = (const float2*)(trans + mat * 16);
        s2[idx] = __ldg(&src[j]);
    }
    __syncthreads();

    const int m0 = blockIdx.y * SL;       // first slice for this block

    for (int g = blockIdx.x * blockDim.x + threadIdx.x; g < G;
         g += gridDim.x * blockDim.x)
    {
        const int i0 = g * 4;

        if (i0 + 3 < N) {
            // ---- load 4 points once ----
            float4 a = __ldg(&xyz4[g * 3 + 0]);
            float4 b = __ldg(&xyz4[g * 3 + 1]);
            float4 c = __ldg(&xyz4[g * 3 + 2]);
            int4  bt = __ldg(&batch4[g]);

            float x[4], y[4], z[4];
            x[0] = a.x; y[0] = a.y; z[0] = a.z;
            x[1] = a.w; y[1] = b.x; z[1] = b.y;
            x[2] = b.z; y[2] = b.w; z[2] = c.x;
            x[3] = c.y; y[3] = c.z; z[3] = c.w;

            int b0[4];
            b0[0] = bt.x; b0[1] = bt.y; b0[2] = bt.z; b0[3] = bt.w;

            #pragma unroll
            for (int s = 0; s < SL; s++) {
                int m = m0 + s;
                if (m >= M) break;
                int mB = m * BATCH_B;
                long long sliceBase = (long long)m * N;

                float o[12];
                #pragma unroll
                for (int k = 0; k < 4; k++) {
                    int nb = b0[k] + mB;
                    float2 p0 = s2[0 * NMAT + nb];  // r00 r01
                    float2 p1 = s2[1 * NMAT + nb];  // r02 tx
                    float2 p2 = s2[2 * NMAT + nb];  // r10 r11
                    float2 p3 = s2[3 * NMAT + nb];  // r12 ty
                    float2 p4 = s2[4 * NMAT + nb];  // r20 r21
                    float2 p5 = s2[5 * NMAT + nb];  // r22 tz
                    o[k*3+0] = fmaf(p0.x, x[k], fmaf(p0.y, y[k], fmaf(p1.x, z[k], p1.y)));
                    o[k*3+1] = fmaf(p2.x, x[k], fmaf(p2.y, y[k], fmaf(p3.x, z[k], p3.y)));
                    o[k*3+2] = fmaf(p4.x, x[k], fmaf(p4.y, y[k], fmaf(p5.x, z[k], p5.y)));
                }

                float4* outv = (float4*)(out + (sliceBase + i0) * 3);
                outv[0] = make_float4(o[0], o[1], o[2],  o[3]);
                outv[1] = make_float4(o[4], o[5], o[6],  o[7]);
                outv[2] = make_float4(o[8], o[9], o[10], o[11]);

                if (writeBatch) {
                    float4* bo = (float4*)(out + posElems + sliceBase + i0);
                    *bo = make_float4((float)(b0[0] + mB), (float)(b0[1] + mB),
                                      (float)(b0[2] + mB), (float)(b0[3] + mB));
                }
            }
        } else {
            // ---- scalar tail ----
            for (int i = i0; i < N; i++) {
                float px = xyz[i * 3 + 0];
                float py = xyz[i * 3 + 1];
                float pz = xyz[i * 3 + 2];
                int bi = __ldg(&batch[i]);
                for (int s = 0; s < SL; s++) {
                    int m = m0 + s;
                    if (m >= M) break;
                    int nb = bi + m * BATCH_B;
                    float2 p0 = s2[0 * NMAT + nb];
                    float2 p1 = s2[1 * NMAT + nb];
                    float2 p2 = s2[2 * NMAT + nb];
                    float2 p3 = s2[3 * NMAT + nb];
                    float2 p4 = s2[4 * NMAT + nb];
                    float2 p5 = s2[5 * NMAT + nb];
                    long long ob = ((long long)m * N + i) * 3;
                    out[ob + 0] = fmaf(p0.x, px, fmaf(p0.y, py, fmaf(p1.x, pz, p1.y)));
                    out[ob + 1] = fmaf(p2.x, px, fmaf(p2.y, py, fmaf(p3.x, pz, p3.y)));
                    out[ob + 2] = fmaf(p4.x, px, fmaf(p4.y, py, fmaf(p5.x, pz, p5.y)));
                    if (writeBatch)
                        out[posElems + (long long)m * N + i] = (float)nb;
                }
            }
        }
    }
}

extern "C" void kernel_launch(void* const* d_in, const int* in_sizes, int n_in,
                              void* d_out, int out_size) {
    const float* trans = (const float*)d_in[0];   // [M*B, 4, 4]
    const float* xyz   = (const float*)d_in[1];   // [N, 3]
    const int*   batch = (const int*)d_in[2];     // [N]

    int numMat = in_sizes[0] / 16;        // M*B (= 128)
    int M      = numMat / BATCH_B;        // 8
    int N      = in_sizes[2];             // 500000

    long long posElems = (long long)M * N * 3;
    int writeBatch = ((long long)out_size >= posElems + (long long)M * N) ? 1 : 0;

    int G = (N + 3) / 4;                  // 4-point groups
    int threads = 256;
    int blocksX = (G + threads - 1) / threads;
    if (blocksX > 65535) blocksX = 65535;
    int blocksY = (M + SL - 1) / SL;      // slice groups

    dim3 grid(blocksX, blocksY, 1);
    se3_kernel<<<grid, threads>>>(
        trans,
        (const float4*)xyz, xyz,
        (const int4*)batch, batch,
        (float*)d_out,
        N, G, M, posElems, writeBatch);
}